// round 6
// baseline (speedup 1.0000x reference)
#include <cuda_runtime.h>

#define NN 200000
#define EE 600000
#define GG 8192
#define HH 128

#define SCT 512
#define SCE 4
#define SCCHUNK (SCT * SCE)                      // 2048
#define SCB ((NN + SCCHUNK - 1) / SCCHUNK)       // 98

// Scratch (allocation-free rule: __device__ globals)
__device__ float g_dinv[NN];
__device__ int   g_cnt_i[NN];
__device__ int   g_rowptr[NN + 1];
__device__ int   g_cursor[NN];
__device__ int   g_col[EE];
__device__ float g_coef[EE];
__device__ int   g_bsum[SCB];
__device__ float g_h[(long long)NN * HH];
__device__ float g_agg[(long long)NN * HH];
__device__ float g_cntf[GG];

// ---------------- degree / counts ----------------
__global__ void k_init() {
    int i = blockIdx.x * blockDim.x + threadIdx.x;
    if (i < NN) g_cnt_i[i] = 0;
}

__global__ void k_count(const int* __restrict__ dst) {
    int e = blockIdx.x * blockDim.x + threadIdx.x;
    if (e < EE) atomicAdd(&g_cnt_i[__ldg(&dst[e])], 1);
}

__global__ void k_dinv() {
    int i = blockIdx.x * blockDim.x + threadIdx.x;
    if (i < NN) g_dinv[i] = rsqrtf(1.0f + (float)g_cnt_i[i]);
}

// ---------------- exclusive scan of g_cnt_i -> g_rowptr ----------------
__global__ void k_scan1() {
    __shared__ int wsum[SCT / 32];
    int t = threadIdx.x, b = blockIdx.x;
    int base = b * SCCHUNK + t * SCE;
    int s = 0;
    #pragma unroll
    for (int i = 0; i < SCE; i++) {
        int idx = base + i;
        if (idx < NN) s += g_cnt_i[idx];
    }
    int lane = t & 31, wid = t >> 5;
    #pragma unroll
    for (int o = 16; o > 0; o >>= 1) s += __shfl_down_sync(0xffffffffu, s, o);
    if (lane == 0) wsum[wid] = s;
    __syncthreads();
    if (wid == 0) {
        int v = (lane < SCT / 32) ? wsum[lane] : 0;
        #pragma unroll
        for (int o = 16; o > 0; o >>= 1) v += __shfl_down_sync(0xffffffffu, v, o);
        if (lane == 0) g_bsum[b] = v;
    }
}

__global__ void k_scan2() {
    if (threadIdx.x == 0) {
        int run = 0;
        for (int b = 0; b < SCB; b++) { int t = g_bsum[b]; g_bsum[b] = run; run += t; }
        g_rowptr[NN] = run;
    }
}

__global__ void k_scan3() {
    __shared__ int wsum[SCT / 32];
    __shared__ int wexcl[SCT / 32];
    int t = threadIdx.x, b = blockIdx.x;
    int base = b * SCCHUNK + t * SCE;
    int p[SCE];
    int run = 0;
    #pragma unroll
    for (int i = 0; i < SCE; i++) {
        int idx = base + i;
        int e = (idx < NN) ? g_cnt_i[idx] : 0;
        p[i] = run; run += e;
    }
    int lane = t & 31, wid = t >> 5;
    int v = run;
    #pragma unroll
    for (int o = 1; o < 32; o <<= 1) {
        int u = __shfl_up_sync(0xffffffffu, v, o);
        if (lane >= o) v += u;
    }
    int texcl = v - run;
    if (lane == 31) wsum[wid] = v;
    __syncthreads();
    if (wid == 0) {
        int w = (lane < SCT / 32) ? wsum[lane] : 0;
        int vv = w;
        #pragma unroll
        for (int o = 1; o < 32; o <<= 1) {
            int u = __shfl_up_sync(0xffffffffu, vv, o);
            if (lane >= o) vv += u;
        }
        if (lane < SCT / 32) wexcl[lane] = vv - w;
    }
    __syncthreads();
    int off = g_bsum[b] + wexcl[wid] + texcl;
    #pragma unroll
    for (int i = 0; i < SCE; i++) {
        int idx = base + i;
        if (idx < NN) { g_rowptr[idx] = off + p[i]; g_cursor[idx] = off + p[i]; }
    }
}

// ---------------- CSR fill ----------------
__global__ void k_fill(const int* __restrict__ src, const int* __restrict__ dst) {
    int e = blockIdx.x * blockDim.x + threadIdx.x;
    if (e >= EE) return;
    int s = __ldg(&src[e]), d = __ldg(&dst[e]);
    int pos = atomicAdd(&g_cursor[d], 1);
    g_col[pos]  = s;
    g_coef[pos] = g_dinv[s] * g_dinv[d];
}

// ---------------- fused layer: aggregate + GEMM (+ pool epilogue) ----------
// LAYER 0: A = Agg(x) (K=30), out: g_h   = relu(A@W1 + b1)
// LAYER 1: A = Agg(g_h) (K=128), out: g_agg = relu(A@W2 + b2)
// LAYER 2: A = Agg(g_agg) (K=128), epilogue: out[batch[r]] += relu(A@W3 + b3)
// Block: 128 rows x 128 cols, 8x8/thread, BK=32. Aggregation is done per
// k-chunk directly into As[k][m] (warp per row, lane = k within chunk).
template<int LAYER>
__global__ __launch_bounds__(256, 2) void k_layer(
    const float* __restrict__ x, const float* __restrict__ W,
    const float* __restrict__ bias, const int* __restrict__ batch,
    float* __restrict__ out)
{
    constexpr int K = (LAYER == 0) ? 30 : 128;
    __shared__ float As[32][132];   // [k][m]
    __shared__ float Ws[32][132];   // [k][n]
    const int tid  = threadIdx.x;
    const int r0   = blockIdx.x * 128;
    const int tx   = tid & 15;
    const int ty   = tid >> 4;
    const int lane = tid & 31;
    const int wp   = tid >> 5;      // 8 warps

    float acc[8][8];
    #pragma unroll
    for (int i = 0; i < 8; i++)
        #pragma unroll
        for (int j = 0; j < 8; j++) acc[i][j] = 0.0f;

    const float* hin = (LAYER == 1) ? g_h : g_agg;   // LAYER 0 ignores

    for (int k0 = 0; k0 < K; k0 += 32) {
        // Phase A: aggregate this block's 128 rows for k in [k0, k0+32)
        for (int rr = 0; rr < 16; rr++) {
            int r  = wp * 16 + rr;
            int gr = r0 + r;
            float a = 0.0f;
            if (gr < NN) {
                int beg = __ldg(&g_rowptr[gr]);
                int end = __ldg(&g_rowptr[gr + 1]);
                float dv = g_dinv[gr];
                float d2 = dv * dv;
                if (LAYER == 0) {
                    if (lane < 30) a = __ldg(&x[(long long)gr * 30 + lane]) * d2;
                    for (int j = beg; j < end; j++) {
                        int s   = __ldg(&g_col[j]);
                        float c = __ldg(&g_coef[j]);
                        if (lane < 30) a += __ldg(&x[(long long)s * 30 + lane]) * c;
                    }
                } else {
                    a = hin[(long long)gr * 128 + k0 + lane] * d2;
                    for (int j = beg; j < end; j++) {
                        int s   = __ldg(&g_col[j]);
                        float c = __ldg(&g_coef[j]);
                        a += __ldg(&hin[(long long)s * 128 + k0 + lane]) * c;
                    }
                }
            }
            As[lane][r] = a;
        }
        // Phase B: load W chunk
        #pragma unroll
        for (int i = 0; i < 16; i++) {
            int f  = i * 256 + tid;
            int kk = f >> 7, n = f & 127;
            int gk = k0 + kk;
            Ws[kk][n] = (gk < K) ? __ldg(&W[gk * 128 + n]) : 0.0f;
        }
        __syncthreads();

        #pragma unroll
        for (int kk = 0; kk < 32; kk++) {
            float4 a0 = *(const float4*)&As[kk][ty * 8];
            float4 a1 = *(const float4*)&As[kk][ty * 8 + 4];
            float4 b0 = *(const float4*)&Ws[kk][tx * 8];
            float4 b1 = *(const float4*)&Ws[kk][tx * 8 + 4];
            float a[8] = {a0.x, a0.y, a0.z, a0.w, a1.x, a1.y, a1.z, a1.w};
            float b[8] = {b0.x, b0.y, b0.z, b0.w, b1.x, b1.y, b1.z, b1.w};
            #pragma unroll
            for (int i = 0; i < 8; i++)
                #pragma unroll
                for (int j = 0; j < 8; j++)
                    acc[i][j] += a[i] * b[j];
        }
        __syncthreads();
    }

    float4 bb0 = ((const float4*)bias)[tx * 2];
    float4 bb1 = ((const float4*)bias)[tx * 2 + 1];
    float bv[8] = {bb0.x, bb0.y, bb0.z, bb0.w, bb1.x, bb1.y, bb1.z, bb1.w};

    #pragma unroll
    for (int i = 0; i < 8; i++) {
        int gr = r0 + ty * 8 + i;
        if (gr >= NN) continue;
        float v[8];
        #pragma unroll
        for (int j = 0; j < 8; j++) v[j] = fmaxf(acc[i][j] + bv[j], 0.0f);
        if (LAYER < 2) {
            float* hout = (LAYER == 0) ? g_h : g_agg;
            long long base = (long long)gr * 128 + tx * 8;
            *(float4*)&hout[base]     = make_float4(v[0], v[1], v[2], v[3]);
            *(float4*)&hout[base + 4] = make_float4(v[4], v[5], v[6], v[7]);
        } else {
            int g = __ldg(&batch[gr]);
            float* p = out + (long long)g * 128 + tx * 8;
            asm volatile("red.global.add.v4.f32 [%0], {%1, %2, %3, %4};"
                         :: "l"(p), "f"(v[0]), "f"(v[1]), "f"(v[2]), "f"(v[3]) : "memory");
            asm volatile("red.global.add.v4.f32 [%0], {%1, %2, %3, %4};"
                         :: "l"(p + 4), "f"(v[4]), "f"(v[5]), "f"(v[6]), "f"(v[7]) : "memory");
        }
    }
}

// ---------------- pooling aux ----------------
__global__ void k_zero_out(float* __restrict__ out) {
    int i = blockIdx.x * blockDim.x + threadIdx.x;
    if (i < (GG * HH) / 4) ((float4*)out)[i] = make_float4(0.f, 0.f, 0.f, 0.f);
    if (i < GG) g_cntf[i] = 0.0f;
}

__global__ void k_cnt(const int* __restrict__ batch) {
    int i = blockIdx.x * blockDim.x + threadIdx.x;
    if (i < NN) atomicAdd(&g_cntf[__ldg(&batch[i])], 1.0f);
}

__global__ void k_div(float* __restrict__ out) {
    int i = blockIdx.x * blockDim.x + threadIdx.x;
    if (i < GG * HH) {
        float c = g_cntf[i >> 7];
        out[i] *= 1.0f / fmaxf(c, 1.0f);
    }
}

// ---------------- launch ----------------
extern "C" void kernel_launch(void* const* d_in, const int* in_sizes, int n_in,
                              void* d_out, int out_size)
{
    const float* x     = (const float*)d_in[0];   // [N, 30]
    const int*   ei    = (const int*)  d_in[1];   // [2, E]
    const int*   batch = (const int*)  d_in[2];   // [N]
    const float* W1    = (const float*)d_in[3];
    const float* b1    = (const float*)d_in[4];
    const float* W2    = (const float*)d_in[5];
    const float* b2    = (const float*)d_in[6];
    const float* W3    = (const float*)d_in[7];
    const float* b3    = (const float*)d_in[8];
    float* out = (float*)d_out;

    const int* src = ei;
    const int* dst = ei + EE;

    // CSR build (by dst) + dinv
    k_init <<<(NN + 255) / 256, 256>>>();
    k_count<<<(EE + 255) / 256, 256>>>(dst);
    k_dinv <<<(NN + 255) / 256, 256>>>();
    k_scan1<<<SCB, SCT>>>();
    k_scan2<<<1, 32>>>();
    k_scan3<<<SCB, SCT>>>();
    k_fill <<<(EE + 255) / 256, 256>>>(src, dst);

    // Pool prep (out must be zero before layer 3's RED epilogue)
    k_zero_out<<<(GG * HH / 4 + 255) / 256, 256>>>(out);
    k_cnt     <<<(NN + 255) / 256, 256>>>(batch);

    const int GB = (NN + 127) / 128;          // 1563 blocks

    k_layer<0><<<GB, 256>>>(x, W1, b1, nullptr, nullptr);
    k_layer<1><<<GB, 256>>>(nullptr, W2, b2, nullptr, nullptr);
    k_layer<2><<<GB, 256>>>(nullptr, W3, b3, batch, out);

    k_div<<<(GG * HH + 255) / 256, 256>>>(out);
}

// round 7
// speedup vs baseline: 3.2650x; 3.2650x over previous
#include <cuda_runtime.h>
#include <cstdint>

#define NN 200000
#define EE 600000
#define GG 8192
#define HH 128

#define SCT 512
#define SCE 4
#define SCCHUNK (SCT * SCE)                      // 2048
#define SCB ((NN + SCCHUNK - 1) / SCCHUNK)       // 98

// Scratch (allocation-free rule: __device__ globals)
__device__ float g_dinv[NN];
__device__ int   g_cnt_i[NN];
__device__ int   g_rowptr[NN + 1];
__device__ int   g_cursor[NN];
__device__ int   g_col[EE];
__device__ float g_coef[EE];
__device__ int   g_bsum[SCB];
__device__ float g_h[(long long)NN * HH];
__device__ float g_agg[(long long)NN * HH];
__device__ float g_cntf[GG];

// ---------------- degree / counts ----------------
__global__ void k_init() {
    int i = blockIdx.x * blockDim.x + threadIdx.x;
    if (i < NN) g_cnt_i[i] = 0;
}

__global__ void k_count(const int* __restrict__ dst) {
    int e = blockIdx.x * blockDim.x + threadIdx.x;
    if (e < EE) atomicAdd(&g_cnt_i[__ldg(&dst[e])], 1);
}

__global__ void k_dinv() {
    int i = blockIdx.x * blockDim.x + threadIdx.x;
    if (i < NN) g_dinv[i] = rsqrtf(1.0f + (float)g_cnt_i[i]);
}

// ---------------- exclusive scan of g_cnt_i -> g_rowptr ----------------
__global__ void k_scan1() {
    __shared__ int wsum[SCT / 32];
    int t = threadIdx.x, b = blockIdx.x;
    int base = b * SCCHUNK + t * SCE;
    int s = 0;
    #pragma unroll
    for (int i = 0; i < SCE; i++) {
        int idx = base + i;
        if (idx < NN) s += g_cnt_i[idx];
    }
    int lane = t & 31, wid = t >> 5;
    #pragma unroll
    for (int o = 16; o > 0; o >>= 1) s += __shfl_down_sync(0xffffffffu, s, o);
    if (lane == 0) wsum[wid] = s;
    __syncthreads();
    if (wid == 0) {
        int v = (lane < SCT / 32) ? wsum[lane] : 0;
        #pragma unroll
        for (int o = 16; o > 0; o >>= 1) v += __shfl_down_sync(0xffffffffu, v, o);
        if (lane == 0) g_bsum[b] = v;
    }
}

__global__ void k_scan2() {
    if (threadIdx.x == 0) {
        int run = 0;
        for (int b = 0; b < SCB; b++) { int t = g_bsum[b]; g_bsum[b] = run; run += t; }
        g_rowptr[NN] = run;
    }
}

__global__ void k_scan3() {
    __shared__ int wsum[SCT / 32];
    __shared__ int wexcl[SCT / 32];
    int t = threadIdx.x, b = blockIdx.x;
    int base = b * SCCHUNK + t * SCE;
    int p[SCE];
    int run = 0;
    #pragma unroll
    for (int i = 0; i < SCE; i++) {
        int idx = base + i;
        int e = (idx < NN) ? g_cnt_i[idx] : 0;
        p[i] = run; run += e;
    }
    int lane = t & 31, wid = t >> 5;
    int v = run;
    #pragma unroll
    for (int o = 1; o < 32; o <<= 1) {
        int u = __shfl_up_sync(0xffffffffu, v, o);
        if (lane >= o) v += u;
    }
    int texcl = v - run;
    if (lane == 31) wsum[wid] = v;
    __syncthreads();
    if (wid == 0) {
        int w = (lane < SCT / 32) ? wsum[lane] : 0;
        int vv = w;
        #pragma unroll
        for (int o = 1; o < 32; o <<= 1) {
            int u = __shfl_up_sync(0xffffffffu, vv, o);
            if (lane >= o) vv += u;
        }
        if (lane < SCT / 32) wexcl[lane] = vv - w;
    }
    __syncthreads();
    int off = g_bsum[b] + wexcl[wid] + texcl;
    #pragma unroll
    for (int i = 0; i < SCE; i++) {
        int idx = base + i;
        if (idx < NN) { g_rowptr[idx] = off + p[i]; g_cursor[idx] = off + p[i]; }
    }
}

// ---------------- CSR fill ----------------
__global__ void k_fill(const int* __restrict__ src, const int* __restrict__ dst) {
    int e = blockIdx.x * blockDim.x + threadIdx.x;
    if (e >= EE) return;
    int s = __ldg(&src[e]), d = __ldg(&dst[e]);
    int pos = atomicAdd(&g_cursor[d], 1);
    g_col[pos]  = s;
    g_coef[pos] = g_dinv[s] * g_dinv[d];
}

// ---------------- aggregation (gather) ----------------
// 30-dim: warp per node. aggX[n] = x[n]*dinv^2 + sum_nbr x[s]*coef
// Output row stride 32 into g_agg; lanes 30/31 written as 0 (K=32 padding).
__global__ __launch_bounds__(256) void k_agg30(const float* __restrict__ x) {
    int n = (blockIdx.x * 256 + threadIdx.x) >> 5;
    if (n >= NN) return;
    int lane = threadIdx.x & 31;
    int beg = __ldg(&g_rowptr[n]), end = __ldg(&g_rowptr[n + 1]);
    float dv = g_dinv[n];
    float acc = 0.0f;
    if (lane < 30) acc = __ldg(&x[(long long)n * 30 + lane]) * dv * dv;
    for (int j = beg; j < end; j++) {
        int s = __ldg(&g_col[j]);
        float c = __ldg(&g_coef[j]);
        if (lane < 30) acc += __ldg(&x[(long long)s * 30 + lane]) * c;
    }
    g_agg[(long long)n * 32 + lane] = (lane < 30) ? acc : 0.0f;
}

// 128-dim: warp per node, lane handles one float4.
// g_agg[n] = g_h[n]*dinv^2 + sum_nbr g_h[s]*coef
__global__ __launch_bounds__(256) void k_agg128() {
    int n = (blockIdx.x * 256 + threadIdx.x) >> 5;
    if (n >= NN) return;
    int lane = threadIdx.x & 31;
    int beg = __ldg(&g_rowptr[n]), end = __ldg(&g_rowptr[n + 1]);
    float dv = g_dinv[n];
    const float4* h4 = (const float4*)g_h;
    float4 a = h4[(long long)n * 32 + lane];
    float d2 = dv * dv;
    float4 acc = make_float4(a.x * d2, a.y * d2, a.z * d2, a.w * d2);
    for (int j = beg; j < end; j++) {
        int s = __ldg(&g_col[j]);
        float c = __ldg(&g_coef[j]);
        float4 v = h4[(long long)s * 128 / 4 + lane];
        acc.x += v.x * c; acc.y += v.y * c; acc.z += v.z * c; acc.w += v.w * c;
    }
    ((float4*)g_agg)[(long long)n * 32 + lane] = acc;
}

// ---------------- tf32 helpers ----------------
__device__ __forceinline__ float tf32r(float x) {
    uint32_t u;
    asm("cvt.rna.tf32.f32 %0, %1;" : "=r"(u) : "f"(x));
    return __uint_as_float(u);
}

__device__ __forceinline__ void mma_tf32(float* d, const uint32_t* a, const uint32_t* b) {
    asm volatile(
        "mma.sync.aligned.m16n8k8.row.col.f32.tf32.tf32.f32 "
        "{%0,%1,%2,%3}, {%4,%5,%6,%7}, {%8,%9}, {%0,%1,%2,%3};\n"
        : "+f"(d[0]), "+f"(d[1]), "+f"(d[2]), "+f"(d[3])
        : "r"(a[0]), "r"(a[1]), "r"(a[2]), "r"(a[3]),
          "r"(b[0]), "r"(b[1]));
}

// ---------------- GEMM (tf32 tensor cores) ----------------
// Reads g_agg (row stride LDA), computes relu(g_agg @ W + bias).
// MODE 0: store to g_h.  MODE 1: red.global.add into out[batch[row]*128+col].
// Block 256 thr = 8 warps (2 m x 4 n), block tile 128x128, warp tile 64x32.
template<int KREAL, int LDA, int MODE>
__global__ __launch_bounds__(256, 2) void k_gemm(
    const float* __restrict__ W, const float* __restrict__ bias,
    const int* __restrict__ batch, float* __restrict__ out)
{
    constexpr int KPAD = (KREAL + 31) & ~31;
    __shared__ float As[128][36];   // [m][k], pad 36 (16B-aligned rows, bank-clean)
    __shared__ float Bs[32][132];   // [k][n]
    const int tid  = threadIdx.x;
    const int r0   = blockIdx.x * 128;
    const int lane = tid & 31;
    const int wp   = tid >> 5;
    const int wm   = wp >> 2;       // 0..1  (64 rows each)
    const int wn   = wp & 3;        // 0..3  (32 cols each)

    float acc[4][4][4];             // [mt][nt][frag]
    #pragma unroll
    for (int i = 0; i < 4; i++)
        #pragma unroll
        for (int j = 0; j < 4; j++)
            #pragma unroll
            for (int q = 0; q < 4; q++) acc[i][j][q] = 0.0f;

    for (int k0 = 0; k0 < KPAD; k0 += 32) {
        // Load A chunk (128x32): warp = one row, 32 consecutive k (coalesced)
        #pragma unroll
        for (int i = 0; i < 16; i++) {
            int f   = i * 256 + tid;
            int row = f >> 5, kk = f & 31;
            int gr  = r0 + row;
            float v = 0.0f;
            if (gr < NN) v = g_agg[(long long)gr * LDA + k0 + kk];
            As[row][kk] = tf32r(v);
        }
        // Load W chunk (32x128), coalesced in n
        #pragma unroll
        for (int i = 0; i < 16; i++) {
            int f  = i * 256 + tid;
            int kk = f >> 7, n = f & 127;
            int gk = k0 + kk;
            float v = (gk < KREAL) ? __ldg(&W[gk * 128 + n]) : 0.0f;
            Bs[kk][n] = tf32r(v);
        }
        __syncthreads();

        #pragma unroll
        for (int kq = 0; kq < 4; kq++) {
            const int kb = kq * 8;
            uint32_t afr[4][4];
            #pragma unroll
            for (int mt = 0; mt < 4; mt++) {
                int mr = wm * 64 + mt * 16 + (lane >> 2);
                int kc = kb + (lane & 3);
                afr[mt][0] = __float_as_uint(As[mr][kc]);
                afr[mt][1] = __float_as_uint(As[mr + 8][kc]);
                afr[mt][2] = __float_as_uint(As[mr][kc + 4]);
                afr[mt][3] = __float_as_uint(As[mr + 8][kc + 4]);
            }
            uint32_t bfr[4][2];
            #pragma unroll
            for (int nt = 0; nt < 4; nt++) {
                int nc = wn * 32 + nt * 8 + (lane >> 2);
                int kr = kb + (lane & 3);
                bfr[nt][0] = __float_as_uint(Bs[kr][nc]);
                bfr[nt][1] = __float_as_uint(Bs[kr + 4][nc]);
            }
            #pragma unroll
            for (int mt = 0; mt < 4; mt++)
                #pragma unroll
                for (int nt = 0; nt < 4; nt++)
                    mma_tf32(acc[mt][nt], afr[mt], bfr[nt]);
        }
        __syncthreads();
    }

    // Epilogue: d0,d1 -> (row, col..col+1); d2,d3 -> (row+8, col..col+1)
    #pragma unroll
    for (int mt = 0; mt < 4; mt++) {
        int row  = r0 + wm * 64 + mt * 16 + (lane >> 2);
        int row2 = row + 8;
        #pragma unroll
        for (int nt = 0; nt < 4; nt++) {
            int col = wn * 32 + nt * 8 + (lane & 3) * 2;
            float b0 = __ldg(&bias[col]), b1 = __ldg(&bias[col + 1]);
            float v00 = fmaxf(acc[mt][nt][0] + b0, 0.0f);
            float v01 = fmaxf(acc[mt][nt][1] + b1, 0.0f);
            float v10 = fmaxf(acc[mt][nt][2] + b0, 0.0f);
            float v11 = fmaxf(acc[mt][nt][3] + b1, 0.0f);
            if (MODE == 0) {
                if (row  < NN) *(float2*)&g_h[(long long)row  * 128 + col] = make_float2(v00, v01);
                if (row2 < NN) *(float2*)&g_h[(long long)row2 * 128 + col] = make_float2(v10, v11);
            } else {
                if (row < NN) {
                    int g = __ldg(&batch[row]);
                    float* p = out + (long long)g * 128 + col;
                    asm volatile("red.global.add.v2.f32 [%0], {%1, %2};"
                                 :: "l"(p), "f"(v00), "f"(v01) : "memory");
                }
                if (row2 < NN) {
                    int g = __ldg(&batch[row2]);
                    float* p = out + (long long)g * 128 + col;
                    asm volatile("red.global.add.v2.f32 [%0], {%1, %2};"
                                 :: "l"(p), "f"(v10), "f"(v11) : "memory");
                }
            }
        }
    }
}

// ---------------- pooling aux ----------------
__global__ void k_zero_out(float* __restrict__ out) {
    int i = blockIdx.x * blockDim.x + threadIdx.x;
    if (i < (GG * HH) / 4) ((float4*)out)[i] = make_float4(0.f, 0.f, 0.f, 0.f);
    if (i < GG) g_cntf[i] = 0.0f;
}

__global__ void k_cnt(const int* __restrict__ batch) {
    int i = blockIdx.x * blockDim.x + threadIdx.x;
    if (i < NN) atomicAdd(&g_cntf[__ldg(&batch[i])], 1.0f);
}

__global__ void k_div(float* __restrict__ out) {
    int i = blockIdx.x * blockDim.x + threadIdx.x;
    if (i < GG * HH) {
        float c = g_cntf[i >> 7];
        out[i] *= 1.0f / fmaxf(c, 1.0f);
    }
}

// ---------------- launch ----------------
extern "C" void kernel_launch(void* const* d_in, const int* in_sizes, int n_in,
                              void* d_out, int out_size)
{
    const float* x     = (const float*)d_in[0];   // [N, 30]
    const int*   ei    = (const int*)  d_in[1];   // [2, E]
    const int*   batch = (const int*)  d_in[2];   // [N]
    const float* W1    = (const float*)d_in[3];
    const float* b1    = (const float*)d_in[4];
    const float* W2    = (const float*)d_in[5];
    const float* b2    = (const float*)d_in[6];
    const float* W3    = (const float*)d_in[7];
    const float* b3    = (const float*)d_in[8];
    float* out = (float*)d_out;

    const int* src = ei;
    const int* dst = ei + EE;

    // CSR build (by dst) + dinv
    k_init <<<(NN + 255) / 256, 256>>>();
    k_count<<<(EE + 255) / 256, 256>>>(dst);
    k_dinv <<<(NN + 255) / 256, 256>>>();
    k_scan1<<<SCB, SCT>>>();
    k_scan2<<<1, 32>>>();
    k_scan3<<<SCB, SCT>>>();
    k_fill <<<(EE + 255) / 256, 256>>>(src, dst);

    // Pool prep (out must be zero before layer-3 RED epilogue)
    k_zero_out<<<(GG * HH / 4 + 255) / 256, 256>>>(out);
    k_cnt     <<<(NN + 255) / 256, 256>>>(batch);

    const int GB = (NN + 127) / 128;          // 1563 blocks
    const int AB = (NN * 32 + 255) / 256;     // 25000 warp-per-node blocks

    // Layer 1: agg in 30-dim input space, then h1 = relu(aggX @ W1 + b1)
    k_agg30<<<AB, 256>>>(x);
    k_gemm<30, 32, 0><<<GB, 256>>>(W1, b1, nullptr, nullptr);
    // Layer 2
    k_agg128<<<AB, 256>>>();
    k_gemm<128, 128, 0><<<GB, 256>>>(W2, b2, nullptr, nullptr);
    // Layer 3 (pool fused into epilogue)
    k_agg128<<<AB, 256>>>();
    k_gemm<128, 128, 1><<<GB, 256>>>(W3, b3, batch, out);

    k_div<<<(GG * HH + 255) / 256, 256>>>(out);
}